// round 1
// baseline (speedup 1.0000x reference)
#include <cuda_runtime.h>
#include <cstdint>

#define T_DIM 512
#define B_DIM 32
#define C_DIM 6000
#define L_DIM 32
#define S_DIM 65           // 2*L+1
#define NEGF (-1e30f)

// ---------------- device scratch (no allocations allowed) ----------------
__device__ float g_lp_ext[(size_t)T_DIM * B_DIM * S_DIM];  // ~4.06 MB
__device__ int   g_extcls[B_DIM * S_DIM];
__device__ int   g_allow [B_DIM * S_DIM];
__device__ int   g_len   [B_DIM];
__device__ float g_loss  [B_DIM];

// ---------------- kernel 1: label prep (+ int64/int32 detection) ----------------
__global__ void ctc_prep_kernel(const void* __restrict__ labels_raw) {
    const int tid = threadIdx.x;
    const int BL = B_DIM * L_DIM;

    // Detect whether labels are int64 or int32. If int64 (little-endian),
    // every odd 32-bit word in the first BL words is the high half of a value
    // in [-1, 5999] -> 0 or -1. Random int32 labels violate this w.p. ~1.
    // Reading only BL int32 words stays within bounds for either dtype.
    const int* w = (const int*)labels_raw;
    int bad = 0;
    for (int i = tid; i < BL; i += blockDim.x)
        if (i & 1) { int v = w[i]; if (v != 0 && v != -1) bad = 1; }
    bad = __syncthreads_or(bad);
    const int is64 = !bad;

    __shared__ int s_cnt[B_DIM];
    __shared__ int s_labv[B_DIM * L_DIM];
    if (tid < B_DIM) s_cnt[tid] = 0;
    __syncthreads();

    for (int i = tid; i < BL; i += blockDim.x) {
        long long lab;
        if (is64) lab = ((const long long*)labels_raw)[i];
        else      lab = (long long)((const int*)labels_raw)[i];
        int v = (lab >= 0) ? (int)lab + 1 : 0;   // shift +1, pad -> blank(0)
        s_labv[i] = v;
        if (lab >= 0) atomicAdd(&s_cnt[i / L_DIM], 1);
    }
    __syncthreads();
    if (tid < B_DIM) g_len[tid] = s_cnt[tid];

    for (int i = tid; i < B_DIM * S_DIM; i += blockDim.x) {
        int b = i / S_DIM, s = i % S_DIM;
        int cls = 0, allow = 0;
        if (s & 1) {
            int j = s >> 1;
            cls = s_labv[b * L_DIM + j];
            if (j >= 1 && cls != s_labv[b * L_DIM + j - 1]) allow = 1;
        }
        g_extcls[i] = cls;
        g_allow[i]  = allow;
    }
}

// ---------------- kernel 2: per-row logsumexp + gather of S classes ----------------
// grid = T*B blocks, 256 threads. Row r = t*B + b (matches (T,B,C) layout).
__global__ void __launch_bounds__(256) ctc_rowlse_kernel(const float* __restrict__ inp) {
    const int r   = blockIdx.x;
    const int tid = threadIdx.x;
    const float4* __restrict__ row4 = (const float4*)(inp + (size_t)r * C_DIM);
    const int N4 = C_DIM / 4;  // 1500

    float4 v[6];
    float m = NEGF;
#pragma unroll
    for (int k = 0; k < 6; k++) {
        int i = tid + k * 256;
        float4 x = (i < N4) ? row4[i] : make_float4(NEGF, NEGF, NEGF, NEGF);
        v[k] = x;
        m = fmaxf(m, fmaxf(fmaxf(x.x, x.y), fmaxf(x.z, x.w)));
    }
    // block max
    __shared__ float shm[8];
#pragma unroll
    for (int o = 16; o; o >>= 1) m = fmaxf(m, __shfl_xor_sync(0xffffffffu, m, o));
    if ((tid & 31) == 0) shm[tid >> 5] = m;
    __syncthreads();
    float bm = fmaxf(fmaxf(fmaxf(shm[0], shm[1]), fmaxf(shm[2], shm[3])),
                     fmaxf(fmaxf(shm[4], shm[5]), fmaxf(shm[6], shm[7])));

    float s = 0.f;
#pragma unroll
    for (int k = 0; k < 6; k++) {
        // padded lanes hold NEGF -> exp underflows to 0, no guard needed
        s += __expf(v[k].x - bm) + __expf(v[k].y - bm)
           + __expf(v[k].z - bm) + __expf(v[k].w - bm);
    }
    __shared__ float shs[8];
#pragma unroll
    for (int o = 16; o; o >>= 1) s += __shfl_xor_sync(0xffffffffu, s, o);
    if ((tid & 31) == 0) shs[tid >> 5] = s;
    __syncthreads();
    float tot = (shs[0] + shs[1]) + (shs[2] + shs[3])
              + (shs[4] + shs[5]) + (shs[6] + shs[7]);
    float lse = bm + __logf(tot);

    if (tid < S_DIM) {
        int b   = r % B_DIM;
        int cls = g_extcls[b * S_DIM + tid];
        float lp = inp[(size_t)r * C_DIM + cls] - lse;   // L1/L2 hit (row just read)
        g_lp_ext[(size_t)r * S_DIM + tid] = lp;
    }
}

// ---------------- kernel 3: forward DP, one warp per batch ----------------
__device__ __forceinline__ float lse3f(float a, float b, float c) {
    float m = fmaxf(a, fmaxf(b, c));
    return m + __logf(__expf(a - m) + __expf(b - m) + __expf(c - m));
}

__global__ void ctc_dp_kernel() {
    const unsigned F = 0xffffffffu;
    const int b    = blockIdx.x;
    const int lane = threadIdx.x;

    // lane holds states s = lane (reg0), s = 32+lane (reg1), s = 64 (reg2, lane 0 only)
    const int allow0 = g_allow[b * S_DIM + lane];
    const int allow1 = g_allow[b * S_DIM + 32 + lane];
    const int len    = g_len[b];

    size_t base = (size_t)b * S_DIM;  // t = 0
    float c0 = g_lp_ext[base + lane];
    float c1 = g_lp_ext[base + 32 + lane];
    float c2 = (lane == 0) ? g_lp_ext[base + 64] : 0.f;

    float a0 = NEGF, a1 = NEGF, a2 = NEGF;
    if (lane == 0) a0 = c0;
    if (lane == 1) a0 = (len > 0) ? c0 : NEGF;

    for (int t = 1; t < T_DIM; t++) {
        size_t bb = (size_t)(t * B_DIM + b) * S_DIM;
        // issue next-step loads early (independent of alpha chain)
        float n0 = g_lp_ext[bb + lane];
        float n1 = g_lp_ext[bb + 32 + lane];
        float n2 = (lane == 0) ? g_lp_ext[bb + 64] : 0.f;

        // cross-register boundary values
        float t0_31 = __shfl_sync(F, a0, 31);
        float t0_30 = __shfl_sync(F, a0, 30);
        float t1_31 = __shfl_sync(F, a1, 31);
        float t1_30 = __shfl_sync(F, a1, 30);

        // shift by 1 (alpha[s-1])
        float s1_0 = __shfl_up_sync(F, a0, 1); if (lane == 0) s1_0 = NEGF;
        float s1_1 = __shfl_up_sync(F, a1, 1); if (lane == 0) s1_1 = t0_31;
        float s1_2 = t1_31;                     // s=64 <- s=63 (lane 0 only)

        // shift by 2 (alpha[s-2]), gated by allow_skip
        float s2_0 = __shfl_up_sync(F, a0, 2); if (lane <= 1) s2_0 = NEGF;
        float s2_1 = __shfl_up_sync(F, a1, 2);
        if (lane == 0) s2_1 = t0_30;
        if (lane == 1) s2_1 = t0_31;
        s2_0 = allow0 ? s2_0 : NEGF;
        s2_1 = allow1 ? s2_1 : NEGF;

        float na0 = lse3f(a0, s1_0, s2_0) + n0;
        float na1 = lse3f(a1, s1_1, s2_1) + n1;
        float na2 = (lane == 0) ? (lse3f(a2, s1_2, NEGF) + n2) : NEGF;
        a0 = na0; a1 = na1; a2 = na2;
        (void)c0; (void)c1; (void)c2;
        c0 = n0; c1 = n1; c2 = n2;
    }

    __shared__ float sh[S_DIM];
    sh[lane] = a0;
    sh[32 + lane] = a1;
    if (lane == 0) sh[64] = a2;
    __syncwarp();

    if (lane == 0) {
        int se = 2 * len;                       // <= 64
        float l1 = sh[se];
        float l2 = sh[(se >= 1) ? (se - 1) : 0];
        if (len == 0) l2 = NEGF;
        float m = fmaxf(l1, l2);
        float loss = -(m + __logf(__expf(l1 - m) + __expf(l2 - m)));
        if (!(loss < 1e29f)) loss = 0.f;        // zero_infinity (also catches NaN)
        g_loss[b] = loss;
    }
}

// ---------------- kernel 4: final reduction ----------------
__global__ void ctc_finish_kernel(float* __restrict__ out) {
    float s = 0.f;
#pragma unroll
    for (int i = 0; i < B_DIM; i++) s += g_loss[i];
    out[0] = s / (float)B_DIM / (float)L_DIM;   // .mean() / L
}

// ---------------- launch ----------------
extern "C" void kernel_launch(void* const* d_in, const int* in_sizes, int n_in,
                              void* d_out, int out_size) {
    const float* inp = (const float*)d_in[0];
    const void*  lab = d_in[1];
    (void)in_sizes; (void)n_in; (void)out_size;

    ctc_prep_kernel<<<1, 256>>>(lab);
    ctc_rowlse_kernel<<<T_DIM * B_DIM, 256>>>(inp);
    ctc_dp_kernel<<<B_DIM, 32>>>();
    ctc_finish_kernel<<<1, 1>>>((float*)d_out);
}

// round 2
// speedup vs baseline: 1.4199x; 1.4199x over previous
#include <cuda_runtime.h>
#include <cstdint>

#define T_DIM 512
#define B_DIM 32
#define C_DIM 6000
#define L_DIM 32
#define S_DIM 65           // 2*L+1
#define S_PAD 66           // padded stride so per-lane float2 loads are 8B-aligned
#define NEGF (-1e30f)
#define LOG2E_F 1.4426950408889634f
#define LN2_F   0.6931471805599453f

// ---------------- device scratch (no allocations allowed) ----------------
__device__ float g_lp_ext[(size_t)T_DIM * B_DIM * S_PAD];  // base-2 scaled log-probs
__device__ int   g_extcls[B_DIM * S_DIM];
__device__ int   g_allow [B_DIM * S_DIM];
__device__ int   g_len   [B_DIM];
__device__ float g_loss  [B_DIM];

__device__ __forceinline__ float ex2f(float x) { float y; asm("ex2.approx.f32 %0, %1;" : "=f"(y) : "f"(x)); return y; }
__device__ __forceinline__ float lg2f(float x) { float y; asm("lg2.approx.f32 %0, %1;" : "=f"(y) : "f"(x)); return y; }

// ---------------- kernel 1: label prep (+ int64/int32 detection) ----------------
__global__ void ctc_prep_kernel(const void* __restrict__ labels_raw) {
    const int tid = threadIdx.x;
    const int BL = B_DIM * L_DIM;

    // int64 detection: for LE int64 labels in [-1, 5999], every odd 32-bit word
    // is 0 or -1. Random int32 labels violate this w.p. ~1. Reads stay in-bounds.
    const int* w = (const int*)labels_raw;
    int bad = 0;
    for (int i = tid; i < BL; i += blockDim.x)
        if (i & 1) { int v = w[i]; if (v != 0 && v != -1) bad = 1; }
    bad = __syncthreads_or(bad);
    const int is64 = !bad;

    __shared__ int s_cnt[B_DIM];
    __shared__ int s_labv[B_DIM * L_DIM];
    if (tid < B_DIM) s_cnt[tid] = 0;
    __syncthreads();

    for (int i = tid; i < BL; i += blockDim.x) {
        long long lab;
        if (is64) lab = ((const long long*)labels_raw)[i];
        else      lab = (long long)((const int*)labels_raw)[i];
        int v = (lab >= 0) ? (int)lab + 1 : 0;   // shift +1, pad -> blank(0)
        s_labv[i] = v;
        if (lab >= 0) atomicAdd(&s_cnt[i / L_DIM], 1);
    }
    __syncthreads();
    if (tid < B_DIM) g_len[tid] = s_cnt[tid];

    for (int i = tid; i < B_DIM * S_DIM; i += blockDim.x) {
        int b = i / S_DIM, s = i % S_DIM;
        int cls = 0, allow = 0;
        if (s & 1) {
            int j = s >> 1;
            cls = s_labv[b * L_DIM + j];
            if (j >= 1 && cls != s_labv[b * L_DIM + j - 1]) allow = 1;
        }
        g_extcls[i] = cls;
        g_allow[i]  = allow;
    }
}

// ---------------- kernel 2: per-row logsumexp + gather of S classes ----------------
// grid = T*B blocks, 256 threads. Row r = t*B + b (matches (T,B,C) layout).
__global__ void __launch_bounds__(256) ctc_rowlse_kernel(const float* __restrict__ inp) {
    const int r   = blockIdx.x;
    const int tid = threadIdx.x;
    const float4* __restrict__ row4 = (const float4*)(inp + (size_t)r * C_DIM);
    const int N4 = C_DIM / 4;  // 1500

    float4 v[6];
    float m = NEGF;
#pragma unroll
    for (int k = 0; k < 6; k++) {
        int i = tid + k * 256;
        float4 x = (i < N4) ? row4[i] : make_float4(NEGF, NEGF, NEGF, NEGF);
        v[k] = x;
        m = fmaxf(m, fmaxf(fmaxf(x.x, x.y), fmaxf(x.z, x.w)));
    }
    __shared__ float shm[8];
#pragma unroll
    for (int o = 16; o; o >>= 1) m = fmaxf(m, __shfl_xor_sync(0xffffffffu, m, o));
    if ((tid & 31) == 0) shm[tid >> 5] = m;
    __syncthreads();
    float bm = fmaxf(fmaxf(fmaxf(shm[0], shm[1]), fmaxf(shm[2], shm[3])),
                     fmaxf(fmaxf(shm[4], shm[5]), fmaxf(shm[6], shm[7])));

    float s = 0.f;
#pragma unroll
    for (int k = 0; k < 6; k++) {
        s += __expf(v[k].x - bm) + __expf(v[k].y - bm)
           + __expf(v[k].z - bm) + __expf(v[k].w - bm);
    }
    __shared__ float shs[8];
#pragma unroll
    for (int o = 16; o; o >>= 1) s += __shfl_xor_sync(0xffffffffu, s, o);
    if ((tid & 31) == 0) shs[tid >> 5] = s;
    __syncthreads();
    float tot = (shs[0] + shs[1]) + (shs[2] + shs[3])
              + (shs[4] + shs[5]) + (shs[6] + shs[7]);
    float lse = bm + __logf(tot);

    if (tid < S_DIM) {
        int b   = r % B_DIM;
        int cls = g_extcls[b * S_DIM + tid];
        // base-2 scaled: alpha recursion runs natively on ex2/lg2
        float lp = (inp[(size_t)r * C_DIM + cls] - lse) * LOG2E_F;
        g_lp_ext[(size_t)r * S_PAD + tid] = lp;
    }
}

// ---------------- kernel 3: forward DP, one warp per batch ----------------
// Lane l holds states 2l (blank, aE) and 2l+1 (label, aO); state 64 in a2.
// Blank update: lse2(aE, o_prev). Label update: lse3(aO, aE, gated o_prev).
// Only 2 shuffles per step; lp loads are float2, prefetched 2 steps ahead.
__global__ void ctc_dp_kernel() {
    const unsigned F = 0xffffffffu;
    const int b    = blockIdx.x;
    const int lane = threadIdx.x;

    const int   len    = g_len[b];
    const int   allowO = g_allow[b * S_DIM + 2 * lane + 1];  // skip gate for state 2l+1
    const float gateO  = allowO ? 0.f : NEGF;                // add-style gate unusable; use select below

    #define ADDR(t) (((size_t)(t) * B_DIM + b) * S_PAD)

    float2 v0 = *(const float2*)(g_lp_ext + ADDR(0) + 2 * lane);
    float  w0 = g_lp_ext[ADDR(0) + 64];
    (void)w0; (void)gateO;

    float aE = (lane == 0) ? v0.x : NEGF;
    float aO = (lane == 0 && len > 0) ? v0.y : NEGF;
    float a2 = NEGF;

    // prefetch depth 2
    float2 v1 = *(const float2*)(g_lp_ext + ADDR(1) + 2 * lane);
    float  w1 = g_lp_ext[ADDR(1) + 64];
    float2 v2 = *(const float2*)(g_lp_ext + ADDR(2) + 2 * lane);
    float  w2 = g_lp_ext[ADDR(2) + 64];

    for (int t = 1; t < T_DIM; t++) {
        float2 v = v1; float w = w1;
        v1 = v2;       w1 = w2;
        int tp = (t + 2 < T_DIM) ? (t + 2) : (T_DIM - 1);
        v2 = *(const float2*)(g_lp_ext + ADDR(tp) + 2 * lane);
        w2 = g_lp_ext[ADDR(tp) + 64];

        float oPrev = __shfl_up_sync(F, aO, 1);        // alpha[2l-1]
        float o31   = __shfl_sync(F, aO, 31);          // alpha[63] (for state 64)
        if (lane == 0) oPrev = NEGF;

        // blank state 2l: preds {2l, 2l-1}
        float m1 = fmaxf(aE, oPrev);
        float nE = m1 + lg2f(ex2f(aE - m1) + ex2f(oPrev - m1)) + v.x;

        // label state 2l+1: preds {2l+1, 2l, 2l-1 if allowed}
        float og = allowO ? oPrev : NEGF;
        float m2 = fmaxf(aO, fmaxf(aE, og));
        float nO = m2 + lg2f(ex2f(aO - m2) + ex2f(aE - m2) + ex2f(og - m2)) + v.y;

        // final blank state 64: preds {64, 63} (computed uniformly on all lanes)
        float m3 = fmaxf(a2, o31);
        float n2 = m3 + lg2f(ex2f(a2 - m3) + ex2f(o31 - m3)) + w;

        aE = nE; aO = nO; a2 = n2;
    }

    __shared__ float sh[S_PAD];
    sh[2 * lane]     = aE;
    sh[2 * lane + 1] = aO;
    if (lane == 0) sh[64] = a2;
    __syncwarp();

    if (lane == 0) {
        int se = 2 * len;                                // <= 64
        float l1 = sh[se];
        float l2 = (len > 0) ? sh[se - 1] : NEGF;
        float m  = fmaxf(l1, l2);
        float res  = m + lg2f(ex2f(l1 - m) + ex2f(l2 - m));  // base-2 domain
        float loss = -res * LN2_F;                            // back to natural log
        if (!(loss < 1e29f)) loss = 0.f;                      // zero_infinity (+NaN guard)
        g_loss[b] = loss;
    }
    #undef ADDR
}

// ---------------- kernel 4: final reduction ----------------
__global__ void ctc_finish_kernel(float* __restrict__ out) {
    float s = g_loss[threadIdx.x];
#pragma unroll
    for (int o = 16; o; o >>= 1) s += __shfl_xor_sync(0xffffffffu, s, o);
    if (threadIdx.x == 0)
        out[0] = s / (float)B_DIM / (float)L_DIM;   // .mean() / L
}

// ---------------- launch ----------------
extern "C" void kernel_launch(void* const* d_in, const int* in_sizes, int n_in,
                              void* d_out, int out_size) {
    const float* inp = (const float*)d_in[0];
    const void*  lab = d_in[1];
    (void)in_sizes; (void)n_in; (void)out_size;

    ctc_prep_kernel<<<1, 256>>>(lab);
    ctc_rowlse_kernel<<<T_DIM * B_DIM, 256>>>(inp);
    ctc_dp_kernel<<<B_DIM, 32>>>();
    ctc_finish_kernel<<<1, 32>>>((float*)d_out);
}